// round 1
// baseline (speedup 1.0000x reference)
#include <cuda_runtime.h>
#include <cstddef>

// Problem constants (from reference)
#define FANOUT 10
#define N0_SZ 1362944
#define N1_SZ 123904
#define N2_SZ 11264
#define SEEDS_SZ 1024
#define IN_DIM 256
#define H_DIM 512
#define C_DIM 256

// Scratch: __device__ globals (allocation-free rule)
__device__ __align__(16) float g_neigh0[(size_t)N1_SZ * IN_DIM];   // 127 MB
__device__ __align__(16) float g_h1[(size_t)N1_SZ * H_DIM];        // 254 MB
__device__ __align__(16) float g_neigh1[(size_t)N2_SZ * H_DIM];    // 23 MB
__device__ __align__(16) float g_h2[(size_t)N2_SZ * H_DIM];        // 23 MB
__device__ __align__(16) float g_neigh2[(size_t)SEEDS_SZ * H_DIM]; // 2 MB

// ---------------------------------------------------------------------------
// Gather-mean: out[d, :] = mean_{e<10} h[src[d*10+e], :]
// grid.x = num_dst, block.x = dim/4. Consecutive threads read consecutive
// float4s of the same source row -> coalesced; 10 independent loads -> MLP=10.
// ---------------------------------------------------------------------------
__global__ void gather_mean_kernel(const float* __restrict__ h,
                                   const int* __restrict__ src,
                                   float* __restrict__ out,
                                   int dim4) {
    const int d = blockIdx.x;
    const int c = threadIdx.x;
    const int* s = src + (size_t)d * FANOUT;
    const float4* h4 = (const float4*)h;

    float4 acc = make_float4(0.f, 0.f, 0.f, 0.f);
#pragma unroll
    for (int e = 0; e < FANOUT; ++e) {
        int r = __ldg(s + e);
        float4 v = __ldg(h4 + (size_t)r * dim4 + c);
        acc.x += v.x; acc.y += v.y; acc.z += v.z; acc.w += v.w;
    }
    const float inv = 1.0f / FANOUT;
    float4 o = make_float4(acc.x * inv, acc.y * inv, acc.z * inv, acc.w * inv);
    ((float4*)out)[(size_t)d * dim4 + c] = o;
}

// ---------------------------------------------------------------------------
// Fused dual-GEMM: C = relu?(A0 @ W0 + A1 @ W1 + b)
//   A0, A1: [M, K] row-major.  W0, W1: [K, N] row-major.  C: [M, N].
// Tile: BM=128, BN=128, BK=16; 256 threads, 8x8 per-thread register tile.
// All M, N, K are multiples of the tile dims -> no bounds checks.
// ---------------------------------------------------------------------------
template <bool RELU>
__global__ __launch_bounds__(256, 2)
void sage_gemm_kernel(const float* __restrict__ A0, const float* __restrict__ A1,
                      const float* __restrict__ W0, const float* __restrict__ W1,
                      const float* __restrict__ bias, float* __restrict__ C,
                      int K, int N) {
    constexpr int BM = 128, BN = 128, BK = 16;
    __shared__ float As[BK][BM + 4];   // +4 pad: spreads transpose-store banks
    __shared__ float Ws[BK][BN];

    const int tid = threadIdx.x;
    const int tx = tid & 15;   // n-direction (8 cols each)
    const int ty = tid >> 4;   // m-direction (8 rows each)
    const int m0 = blockIdx.y * BM;
    const int n0 = blockIdx.x * BN;

    float acc[8][8];
#pragma unroll
    for (int i = 0; i < 8; ++i)
#pragma unroll
        for (int j = 0; j < 8; ++j) acc[i][j] = 0.f;

#pragma unroll
    for (int pair = 0; pair < 2; ++pair) {
        const float* A = pair ? A1 : A0;
        const float* W = pair ? W1 : W0;

        for (int k0 = 0; k0 < K; k0 += BK) {
            // --- load A tile (128 x 16) as float4, store transposed ---
#pragma unroll
            for (int l = 0; l < 2; ++l) {
                int f   = tid + l * 256;        // 512 float4s total
                int row = f >> 2;               // 0..127
                int c4  = f & 3;                // 0..3
                float4 v = __ldg((const float4*)(A + (size_t)(m0 + row) * K + k0) + c4);
                As[c4 * 4 + 0][row] = v.x;
                As[c4 * 4 + 1][row] = v.y;
                As[c4 * 4 + 2][row] = v.z;
                As[c4 * 4 + 3][row] = v.w;
            }
            // --- load W tile (16 x 128) as float4 ---
#pragma unroll
            for (int l = 0; l < 2; ++l) {
                int f   = tid + l * 256;
                int row = f >> 5;               // 0..15
                int c4  = f & 31;               // 0..31
                float4 v = __ldg((const float4*)(W + (size_t)(k0 + row) * N + n0) + c4);
                ((float4*)Ws[row])[c4] = v;
            }
            __syncthreads();

#pragma unroll
            for (int k = 0; k < BK; ++k) {
                float a[8], b[8];
#pragma unroll
                for (int i = 0; i < 8; ++i) a[i] = As[k][ty * 8 + i];
#pragma unroll
                for (int j = 0; j < 8; ++j) b[j] = Ws[k][tx * 8 + j];
#pragma unroll
                for (int i = 0; i < 8; ++i)
#pragma unroll
                    for (int j = 0; j < 8; ++j)
                        acc[i][j] += a[i] * b[j];
            }
            __syncthreads();
        }
    }

    // --- epilogue: + bias, optional ReLU, float4 stores ---
#pragma unroll
    for (int i = 0; i < 8; ++i) {
        int m = m0 + ty * 8 + i;
#pragma unroll
        for (int j = 0; j < 8; j += 4) {
            int n = n0 + tx * 8 + j;
            float4 o;
            o.x = acc[i][j + 0] + __ldg(bias + n + 0);
            o.y = acc[i][j + 1] + __ldg(bias + n + 1);
            o.z = acc[i][j + 2] + __ldg(bias + n + 2);
            o.w = acc[i][j + 3] + __ldg(bias + n + 3);
            if (RELU) {
                o.x = fmaxf(o.x, 0.f); o.y = fmaxf(o.y, 0.f);
                o.z = fmaxf(o.z, 0.f); o.w = fmaxf(o.w, 0.f);
            }
            *(float4*)(C + (size_t)m * N + n) = o;
        }
    }
}

// ---------------------------------------------------------------------------
extern "C" void kernel_launch(void* const* d_in, const int* in_sizes, int n_in,
                              void* d_out, int out_size) {
    const float* x   = (const float*)d_in[0];
    const float* Ws0 = (const float*)d_in[1];
    const float* Wn0 = (const float*)d_in[2];
    const float* b0  = (const float*)d_in[3];
    const float* Ws1 = (const float*)d_in[4];
    const float* Wn1 = (const float*)d_in[5];
    const float* b1  = (const float*)d_in[6];
    const float* Ws2 = (const float*)d_in[7];
    const float* Wn2 = (const float*)d_in[8];
    const float* b2  = (const float*)d_in[9];
    const int*   e0  = (const int*)d_in[10];
    const int*   e1  = (const int*)d_in[11];
    const int*   e2  = (const int*)d_in[12];
    float* out = (float*)d_out;

    float *neigh0, *h1, *neigh1, *h2, *neigh2;
    cudaGetSymbolAddress((void**)&neigh0, g_neigh0);
    cudaGetSymbolAddress((void**)&h1,     g_h1);
    cudaGetSymbolAddress((void**)&neigh1, g_neigh1);
    cudaGetSymbolAddress((void**)&h2,     g_h2);
    cudaGetSymbolAddress((void**)&neigh2, g_neigh2);

    // ---- Layer 0: x[1362944,256] -> h1[123904,512], ReLU ----
    gather_mean_kernel<<<N1_SZ, IN_DIM / 4>>>(x, e0, neigh0, IN_DIM / 4);
    sage_gemm_kernel<true><<<dim3(H_DIM / 128, N1_SZ / 128), 256>>>(
        x, neigh0, Ws0, Wn0, b0, h1, IN_DIM, H_DIM);

    // ---- Layer 1: h1[123904,512] -> h2[11264,512], ReLU ----
    gather_mean_kernel<<<N2_SZ, H_DIM / 4>>>(h1, e1, neigh1, H_DIM / 4);
    sage_gemm_kernel<true><<<dim3(H_DIM / 128, N2_SZ / 128), 256>>>(
        h1, neigh1, Ws1, Wn1, b1, h2, H_DIM, H_DIM);

    // ---- Layer 2: h2[11264,512] -> out[1024,256], no activation ----
    gather_mean_kernel<<<SEEDS_SZ, H_DIM / 4>>>(h2, e2, neigh2, H_DIM / 4);
    sage_gemm_kernel<false><<<dim3(C_DIM / 128, SEEDS_SZ / 128), 256>>>(
        h2, neigh2, Ws2, Wn2, b2, out, H_DIM, C_DIM);
}

// round 3
// speedup vs baseline: 2.5315x; 2.5315x over previous
#include <cuda_runtime.h>
#include <cstdint>
#include <cstddef>

// ---------------- problem constants ----------------
#define FANOUT 10
#define N0_SZ 1362944
#define N1_SZ 123904
#define N2_SZ 11264
#define SEEDS_SZ 1024
#define IN_DIM 256
#define H_DIM 512
#define C_DIM 256

// ---------------- device scratch (allocation-free rule) ----------------
__device__ __align__(16) float g_neigh0[(size_t)N1_SZ * IN_DIM];
__device__ __align__(16) float g_h1[(size_t)N1_SZ * H_DIM];
__device__ __align__(16) float g_neigh1[(size_t)N2_SZ * H_DIM];
__device__ __align__(16) float g_h2[(size_t)N2_SZ * H_DIM];
__device__ __align__(16) float g_neigh2[(size_t)SEEDS_SZ * H_DIM];
// transposed + tf32-rounded weights: Wt[n][k] = tf32(W[k][n])
__device__ __align__(16) float g_Wt0s[(size_t)H_DIM * IN_DIM];
__device__ __align__(16) float g_Wt0n[(size_t)H_DIM * IN_DIM];
__device__ __align__(16) float g_Wt1s[(size_t)H_DIM * H_DIM];
__device__ __align__(16) float g_Wt1n[(size_t)H_DIM * H_DIM];
__device__ __align__(16) float g_Wt2s[(size_t)C_DIM * H_DIM];
__device__ __align__(16) float g_Wt2n[(size_t)C_DIM * H_DIM];

// ---------------- helpers (all portable sm_80+ PTX) ----------------
__device__ __forceinline__ uint32_t smem_u32(const void* p) {
    uint32_t a;
    asm("{ .reg .u64 t; cvta.to.shared.u64 t, %1; cvt.u32.u64 %0, t; }" : "=r"(a) : "l"(p));
    return a;
}
__device__ __forceinline__ float cvt_tf32(float x) {
    float r; asm("cvt.rna.tf32.f32 %0, %1;" : "=f"(r) : "f"(x)); return r;
}
__device__ __forceinline__ uint32_t f2tf(float x) {
    return __float_as_uint(cvt_tf32(x));
}
__device__ __forceinline__ void cp_async16(uint32_t dst, const void* src) {
    asm volatile("cp.async.cg.shared.global [%0], [%1], 16;" :: "r"(dst), "l"(src));
}
#define CP_COMMIT() asm volatile("cp.async.commit_group;" ::: "memory")
#define CP_WAIT(n)  asm volatile("cp.async.wait_group %0;" :: "n"(n) : "memory")

__device__ __forceinline__ void mma_tf32(float c[4],
                                         uint32_t a0, uint32_t a1, uint32_t a2, uint32_t a3,
                                         uint32_t b0, uint32_t b1) {
    asm volatile(
        "mma.sync.aligned.m16n8k8.row.col.f32.tf32.tf32.f32 "
        "{%0,%1,%2,%3}, {%4,%5,%6,%7}, {%8,%9}, {%0,%1,%2,%3};"
        : "+f"(c[0]), "+f"(c[1]), "+f"(c[2]), "+f"(c[3])
        : "r"(a0), "r"(a1), "r"(a2), "r"(a3), "r"(b0), "r"(b1));
}

// ---------------------------------------------------------------------------
// gather-mean: out[d,:] = mean_{e<10} h[src[d*10+e], :]
// ---------------------------------------------------------------------------
__global__ void gather_mean_kernel(const float* __restrict__ h,
                                   const int* __restrict__ src,
                                   float* __restrict__ out, int dim4) {
    const int d = blockIdx.x;
    const int c = threadIdx.x;
    const int* s = src + (size_t)d * FANOUT;
    const float4* h4 = (const float4*)h;
    float4 acc = make_float4(0.f, 0.f, 0.f, 0.f);
#pragma unroll
    for (int e = 0; e < FANOUT; ++e) {
        int r = __ldg(s + e);
        float4 v = __ldg(h4 + (size_t)r * dim4 + c);
        acc.x += v.x; acc.y += v.y; acc.z += v.z; acc.w += v.w;
    }
    const float inv = 1.0f / FANOUT;
    ((float4*)out)[(size_t)d * dim4 + c] =
        make_float4(acc.x * inv, acc.y * inv, acc.z * inv, acc.w * inv);
}

// ---------------------------------------------------------------------------
// W[K,N] -> Wt[N,K] with tf32 RNA rounding. grid(N/32, K/32), block(32,8)
// ---------------------------------------------------------------------------
__global__ void transpose_tf32_kernel(const float* __restrict__ W,
                                      float* __restrict__ Wt, int K, int N) {
    __shared__ float t[32][33];
    int bx = blockIdx.x * 32, by = blockIdx.y * 32;
#pragma unroll
    for (int i = threadIdx.y; i < 32; i += 8)
        t[i][threadIdx.x] = __ldg(W + (size_t)(by + i) * N + bx + threadIdx.x);
    __syncthreads();
#pragma unroll
    for (int i = threadIdx.y; i < 32; i += 8)
        Wt[(size_t)(bx + i) * K + by + threadIdx.x] = cvt_tf32(t[threadIdx.x][i]);
}

// ---------------------------------------------------------------------------
// tf32 mma.sync dual-GEMM: C[M,N] = relu?(A0 @ W0 + A1 @ W1 + b)
// A0,A1: [M,K] fp32 row-major. B0t,B1t: [N,K] tf32 (pre-transposed weights).
// CTA 128x128, BK=32, 8 warps (2m x 4n), warp tile 64x32, double-buffered
// cp.async staging. All dims divide tiles exactly (no bounds checks).
// Smem rows padded to 36 floats -> conflict-free fragment loads.
// ---------------------------------------------------------------------------
#define PADK 36
#define TILE_F (128 * PADK)            // floats per operand tile buffer
#define SMEM_GEMM_BYTES (4 * TILE_F * 4)  // 2 ops x 2 bufs

template <bool RELU>
__global__ __launch_bounds__(256, 2)
void sage_mma_gemm(const float* __restrict__ A0, const float* __restrict__ A1,
                   const float* __restrict__ B0t, const float* __restrict__ B1t,
                   const float* __restrict__ bias, float* __restrict__ C,
                   int K, int N) {
    extern __shared__ float sm[];
    const uint32_t sbase = smem_u32(sm);
    const int tid = threadIdx.x, lane = tid & 31, w = tid >> 5;
    const int wm = w >> 2, wn = w & 3;         // 2 x 4 warp grid
    const int m0 = blockIdx.y * 128, n0 = blockIdx.x * 128;
    const int kc = K / 32;                     // chunks per operand pair
    const int T = 2 * kc;

    float acc[4][4][4];
#pragma unroll
    for (int mi = 0; mi < 4; ++mi)
#pragma unroll
        for (int ni = 0; ni < 4; ++ni)
#pragma unroll
            for (int r = 0; r < 4; ++r) acc[mi][ni][r] = 0.f;

    const int srow = tid >> 3;      // staging: row this thread covers (per 256-chunk)
    const int sc4  = tid & 7;       // 16B column chunk (0..7)

    auto stage = [&](int chunk, int buf) {
        const int pair = (chunk >= kc) ? 1 : 0;
        const int k0 = (pair ? chunk - kc : chunk) * 32;
        const float* A = pair ? A1 : A0;
        const float* B = pair ? B1t : B0t;
        const uint32_t da = sbase + (uint32_t)buf * (TILE_F * 4);
        const uint32_t db = sbase + (uint32_t)(2 + buf) * (TILE_F * 4);
#pragma unroll
        for (int l = 0; l < 4; ++l) {
            int row = srow + l * 32;
            cp_async16(da + (uint32_t)(row * PADK + sc4 * 4) * 4,
                       A + (size_t)(m0 + row) * K + k0 + sc4 * 4);
        }
#pragma unroll
        for (int l = 0; l < 4; ++l) {
            int row = srow + l * 32;
            cp_async16(db + (uint32_t)(row * PADK + sc4 * 4) * 4,
                       B + (size_t)(n0 + row) * K + k0 + sc4 * 4);
        }
    };

    stage(0, 0);
    CP_COMMIT();
    int buf = 0;
    for (int chunk = 0; chunk < T; ++chunk) {
        if (chunk + 1 < T) {
            stage(chunk + 1, buf ^ 1);
            CP_COMMIT();
            CP_WAIT(1);
        } else {
            CP_WAIT(0);
        }
        __syncthreads();

        const float* As = sm + buf * TILE_F;
        const float* Bs = sm + (2 + buf) * TILE_F;
#pragma unroll
        for (int ks = 0; ks < 4; ++ks) {
            uint32_t a[4][4], b[4][2];
            const int cc = ks * 8 + (lane & 3);
#pragma unroll
            for (int mi = 0; mi < 4; ++mi) {
                const float* p = As + (wm * 64 + mi * 16 + (lane >> 2)) * PADK + cc;
                a[mi][0] = f2tf(p[0]);
                a[mi][1] = f2tf(p[8 * PADK]);
                a[mi][2] = f2tf(p[4]);
                a[mi][3] = f2tf(p[8 * PADK + 4]);
            }
#pragma unroll
            for (int ni = 0; ni < 4; ++ni) {
                const float* p = Bs + (wn * 32 + ni * 8 + (lane >> 2)) * PADK + cc;
                b[ni][0] = __float_as_uint(p[0]);
                b[ni][1] = __float_as_uint(p[4]);
            }
#pragma unroll
            for (int mi = 0; mi < 4; ++mi)
#pragma unroll
                for (int ni = 0; ni < 4; ++ni)
                    mma_tf32(acc[mi][ni], a[mi][0], a[mi][1], a[mi][2], a[mi][3],
                             b[ni][0], b[ni][1]);
        }
        __syncthreads();
        buf ^= 1;
    }

    // epilogue: bias + optional ReLU, float2 stores from fragments
#pragma unroll
    for (int ni = 0; ni < 4; ++ni) {
        const int n = n0 + wn * 32 + ni * 8 + 2 * (lane & 3);
        const float bx = __ldg(bias + n), by = __ldg(bias + n + 1);
#pragma unroll
        for (int mi = 0; mi < 4; ++mi) {
            const int m = m0 + wm * 64 + mi * 16 + (lane >> 2);
            float2 o0 = make_float2(acc[mi][ni][0] + bx, acc[mi][ni][1] + by);
            float2 o1 = make_float2(acc[mi][ni][2] + bx, acc[mi][ni][3] + by);
            if (RELU) {
                o0.x = fmaxf(o0.x, 0.f); o0.y = fmaxf(o0.y, 0.f);
                o1.x = fmaxf(o1.x, 0.f); o1.y = fmaxf(o1.y, 0.f);
            }
            *(float2*)(C + (size_t)m * N + n) = o0;
            *(float2*)(C + (size_t)(m + 8) * N + n) = o1;
        }
    }
}

// ---------------------------------------------------------------------------
extern "C" void kernel_launch(void* const* d_in, const int* in_sizes, int n_in,
                              void* d_out, int out_size) {
    const float* x   = (const float*)d_in[0];
    const float* Ws0 = (const float*)d_in[1];
    const float* Wn0 = (const float*)d_in[2];
    const float* b0  = (const float*)d_in[3];
    const float* Ws1 = (const float*)d_in[4];
    const float* Wn1 = (const float*)d_in[5];
    const float* b1  = (const float*)d_in[6];
    const float* Ws2 = (const float*)d_in[7];
    const float* Wn2 = (const float*)d_in[8];
    const float* b2  = (const float*)d_in[9];
    const int*   e0  = (const int*)d_in[10];
    const int*   e1  = (const int*)d_in[11];
    const int*   e2  = (const int*)d_in[12];
    float* out = (float*)d_out;

    float *neigh0, *h1, *neigh1, *h2, *neigh2;
    float *Wt0s, *Wt0n, *Wt1s, *Wt1n, *Wt2s, *Wt2n;
    cudaGetSymbolAddress((void**)&neigh0, g_neigh0);
    cudaGetSymbolAddress((void**)&h1,     g_h1);
    cudaGetSymbolAddress((void**)&neigh1, g_neigh1);
    cudaGetSymbolAddress((void**)&h2,     g_h2);
    cudaGetSymbolAddress((void**)&neigh2, g_neigh2);
    cudaGetSymbolAddress((void**)&Wt0s,   g_Wt0s);
    cudaGetSymbolAddress((void**)&Wt0n,   g_Wt0n);
    cudaGetSymbolAddress((void**)&Wt1s,   g_Wt1s);
    cudaGetSymbolAddress((void**)&Wt1n,   g_Wt1n);
    cudaGetSymbolAddress((void**)&Wt2s,   g_Wt2s);
    cudaGetSymbolAddress((void**)&Wt2n,   g_Wt2n);

    cudaFuncSetAttribute(sage_mma_gemm<true>,
                         cudaFuncAttributeMaxDynamicSharedMemorySize, SMEM_GEMM_BYTES);
    cudaFuncSetAttribute(sage_mma_gemm<false>,
                         cudaFuncAttributeMaxDynamicSharedMemorySize, SMEM_GEMM_BYTES);

    // weight transposes (+ tf32 rounding)
    transpose_tf32_kernel<<<dim3(H_DIM / 32, IN_DIM / 32), dim3(32, 8)>>>(Ws0, Wt0s, IN_DIM, H_DIM);
    transpose_tf32_kernel<<<dim3(H_DIM / 32, IN_DIM / 32), dim3(32, 8)>>>(Wn0, Wt0n, IN_DIM, H_DIM);
    transpose_tf32_kernel<<<dim3(H_DIM / 32, H_DIM / 32), dim3(32, 8)>>>(Ws1, Wt1s, H_DIM, H_DIM);
    transpose_tf32_kernel<<<dim3(H_DIM / 32, H_DIM / 32), dim3(32, 8)>>>(Wn1, Wt1n, H_DIM, H_DIM);
    transpose_tf32_kernel<<<dim3(C_DIM / 32, H_DIM / 32), dim3(32, 8)>>>(Ws2, Wt2s, H_DIM, C_DIM);
    transpose_tf32_kernel<<<dim3(C_DIM / 32, H_DIM / 32), dim3(32, 8)>>>(Wn2, Wt2n, H_DIM, C_DIM);

    // ---- Layer 0: x[1362944,256] -> h1[123904,512], ReLU ----
    gather_mean_kernel<<<N1_SZ, IN_DIM / 4>>>(x, e0, neigh0, IN_DIM / 4);
    sage_mma_gemm<true><<<dim3(H_DIM / 128, N1_SZ / 128), 256, SMEM_GEMM_BYTES>>>(
        x, neigh0, Wt0s, Wt0n, b0, h1, IN_DIM, H_DIM);

    // ---- Layer 1: h1[123904,512] -> h2[11264,512], ReLU ----
    gather_mean_kernel<<<N2_SZ, H_DIM / 4>>>(h1, e1, neigh1, H_DIM / 4);
    sage_mma_gemm<true><<<dim3(H_DIM / 128, N2_SZ / 128), 256, SMEM_GEMM_BYTES>>>(
        h1, neigh1, Wt1s, Wt1n, b1, h2, H_DIM, H_DIM);

    // ---- Layer 2: h2[11264,512] -> out[1024,256], no activation ----
    gather_mean_kernel<<<SEEDS_SZ, H_DIM / 4>>>(h2, e2, neigh2, H_DIM / 4);
    sage_mma_gemm<false><<<dim3(C_DIM / 128, SEEDS_SZ / 128), 256, SMEM_GEMM_BYTES>>>(
        h2, neigh2, Wt2s, Wt2n, b2, out, H_DIM, C_DIM);
}